// round 13
// baseline (speedup 1.0000x reference)
#include <cuda_runtime.h>
#include <cuda_fp16.h>
#include <cstdint>
#include <math.h>

#define M_DIM 16384
#define K_DIM 4096
#define N_DIM 4096

// fp16 copies of inputs + lse partials (static device scratch)
static __device__ __half g_xh[(size_t)M_DIM * K_DIM];
static __device__ __half g_wh[(size_t)N_DIM * K_DIM];
static __device__ float2 g_part[(size_t)M_DIM * 16];  // [row][nslice] (max,sum)

// ---------------- tile / smem geometry ----------------
constexpr int BM = 128;            // M tile per CTA
constexpr int BN = 256;            // N cols per CTA (single chunk)
constexpr int NSLICE = 16;         // N split across CTAs
constexpr int BK = 64;             // K halves per stage (128 B/row, SW128)
constexpr int NSTAGE = 2;
constexpr int TOTSTG = K_DIM / BK;           // 64 stages per CTA

constexpr uint32_t A_STG = BM * 128;         // 16 KB
constexpr uint32_t B_STG = BN * 128;         // 32 KB
constexpr uint32_t STG   = A_STG + B_STG;    // 48 KB
constexpr uint32_t SMEM_BYTES = NSTAGE * STG + 1024;   // 99328 -> 2 CTAs/SM

__device__ __forceinline__ uint32_t smem_u32(const void* p) {
    uint32_t a;
    asm("{ .reg .u64 t; cvta.to.shared.u64 t, %1; cvt.u32.u64 %0, t; }"
        : "=r"(a) : "l"(p));
    return a;
}
__device__ __forceinline__ uint32_t swz(uint32_t off) {   // SW128, 16B granule
    return off ^ ((off >> 3) & 0x70);
}
__device__ __forceinline__ uint32_t h2_bits(__half2 h) {
    return *reinterpret_cast<uint32_t*>(&h);
}
__device__ __forceinline__ void cp_async16(uint32_t dst, const void* src) {
    asm volatile("cp.async.cg.shared.global [%0], [%1], 16;"
                 :: "r"(dst), "l"(__cvta_generic_to_global(src)) : "memory");
}
#define CP_COMMIT() asm volatile("cp.async.commit_group;" ::: "memory")
#define CP_WAIT(n)  asm volatile("cp.async.wait_group %0;" :: "n"(n) : "memory")

__device__ __forceinline__ void ldsm4(uint32_t* r, uint32_t addr) {
    asm volatile("ldmatrix.sync.aligned.m8n8.x4.shared.b16 {%0,%1,%2,%3}, [%4];"
                 : "=r"(r[0]), "=r"(r[1]), "=r"(r[2]), "=r"(r[3]) : "r"(addr));
}
// fp16-accumulate MMA: D/C are 2 b32 regs (4 halves)
__device__ __forceinline__ void mma16816_h(uint32_t* c, const uint32_t* a, const uint32_t* b) {
    asm volatile(
        "mma.sync.aligned.m16n8k16.row.col.f16.f16.f16.f16 "
        "{%0,%1}, {%2,%3,%4,%5}, {%6,%7}, {%0,%1};"
        : "+r"(c[0]), "+r"(c[1])
        : "r"(a[0]), "r"(a[1]), "r"(a[2]), "r"(a[3]), "r"(b[0]), "r"(b[1]));
}

// ---------------- fp32 -> fp16 conversion: x and W in ONE launch ----------------
__global__ void __launch_bounds__(256)
cvt_xw_kernel(const float4* __restrict__ xs, int nx8,
              const float4* __restrict__ ws, int nw8) {
    const int i = blockIdx.x * 256 + threadIdx.x;
    const float4* src;
    uint4* dst;
    int idx;
    if (i < nx8) {
        src = xs; dst = reinterpret_cast<uint4*>(g_xh); idx = i;
    } else {
        idx = i - nx8;
        if (idx >= nw8) return;
        src = ws; dst = reinterpret_cast<uint4*>(g_wh);
    }
    float4 a = src[2 * idx], b = src[2 * idx + 1];
    uint4 o;
    o.x = h2_bits(__floats2half2_rn(a.x, a.y));
    o.y = h2_bits(__floats2half2_rn(a.z, a.w));
    o.z = h2_bits(__floats2half2_rn(b.x, b.y));
    o.w = h2_bits(__floats2half2_rn(b.z, b.w));
    dst[idx] = o;
}

// ---------------- GEMM + partial logsumexp (per N-slice) ----------------
__global__ void __launch_bounds__(256, 2)
gemm_lse_part_kernel(const float* __restrict__ bias) {
    extern __shared__ char smem_raw[];
    const uint32_t sb0 = smem_u32(smem_raw);
    const uint32_t sb  = (sb0 + 1023u) & ~1023u;   // 1024-align
    char* sptr = smem_raw + (sb - sb0);

    const int tid  = threadIdx.x;
    const int wid  = tid >> 5;            // 0..7
    const int lane = tid & 31;
    const int mt   = blockIdx.x >> 4;     // m-tile (16 consecutive CTAs share A)
    const int ns   = blockIdx.x & 15;     // n-slice
    const int m0   = mt * BM;
    const int n0   = ns * BN;

    const int warpM = (wid >> 2) * 64;    // 0 or 64
    const int warpN = (wid & 3) * 64;     // 0,64,128,192 within BN

    // per-lane ldmatrix byte offsets (pre-swizzle)
    const int matid = lane >> 3, rin = lane & 7;
    int aRow[4], bRow[4];
    #pragma unroll
    for (int mi = 0; mi < 4; mi++)
        aRow[mi] = (warpM + mi * 16 + (matid & 1) * 8 + rin) * 128 + (matid >> 1) * 16;
    #pragma unroll
    for (int p = 0; p < 4; p++)
        bRow[p] = (warpN + p * 16 + (matid >> 1) * 8 + rin) * 128 + (matid & 1) * 16;

    // ---- producer addressing (uniform strides) ----
    const int prow  = tid >> 3;
    const int pc16  = tid & 7;
    const char* srcA = (const char*)(g_xh + ((size_t)(m0 + prow) * K_DIM + pc16 * 8));
    const char* srcB = (const char*)(g_wh + ((size_t)(n0 + prow) * K_DIM + pc16 * 8));
    const uint32_t dstOff = swz((uint32_t)(prow * 128 + pc16 * 16));  // +4096/j commutes

    auto issue_stage = [&](int gs) {
        if (gs < TOTSTG) {
            const uint32_t offK = (uint32_t)gs << 7;   // gs * 128 B into each row
            const uint32_t base = sb + (uint32_t)(gs & 1) * STG;
            #pragma unroll
            for (int j = 0; j < 4; j++)
                cp_async16(base + dstOff + j * 4096,
                           srcA + offK + (size_t)j * (32 * K_DIM * 2));
            #pragma unroll
            for (int j = 0; j < 8; j++)
                cp_async16(base + A_STG + dstOff + j * 4096,
                           srcB + offK + (size_t)j * (32 * K_DIM * 2));
        }
        CP_COMMIT();
    };

    // fp16 accumulators: 4 m-tiles x 8 n-tiles x 2 regs
    uint32_t hacc[4][8][2];
    #pragma unroll
    for (int mi = 0; mi < 4; mi++)
        #pragma unroll
        for (int ni = 0; ni < 8; ni++) { hacc[mi][ni][0] = 0u; hacc[mi][ni][1] = 0u; }

    issue_stage(0);

    #pragma unroll 1
    for (int gs = 0; gs < TOTSTG; ++gs) {
        CP_WAIT(0);                            // stage gs complete (per-warp)
        __syncthreads();                       // visibility + all warps past gs-1

        const uint32_t aB = sb + (uint32_t)(gs & 1) * STG;
        const uint32_t bB = aB + A_STG;
        #pragma unroll
        for (int g = 0; g < 4; g++) {
            uint32_t af[4][4], bt[4][4];
            #pragma unroll
            for (int mi = 0; mi < 4; mi++)
                ldsm4(af[mi], aB + swz((uint32_t)(aRow[mi] + g * 32)));
            #pragma unroll
            for (int p = 0; p < 4; p++)
                ldsm4(bt[p], bB + swz((uint32_t)(bRow[p] + g * 32)));
            if (g == 0)
                issue_stage(gs + 1);           // in the LDS shadow; slot freed by bar
            #pragma unroll
            for (int mi = 0; mi < 4; mi++)
                #pragma unroll
                for (int p = 0; p < 4; p++) {
                    mma16816_h(hacc[mi][2 * p],     af[mi], &bt[p][0]);
                    mma16816_h(hacc[mi][2 * p + 1], af[mi], &bt[p][2]);
                }
        }
    }

    // fold logits (fp16 acc, K complete) into (max, sum)
    const int tg = lane & 3;
    float rm[8], rs[8];
    float bv[8][2];
    #pragma unroll
    for (int ni = 0; ni < 8; ni++) {
        const int nc = n0 + warpN + ni * 8 + tg * 2;
        bv[ni][0] = bias[nc];
        bv[ni][1] = bias[nc + 1];
    }
    #pragma unroll
    for (int mi = 0; mi < 4; mi++) {
        #pragma unroll
        for (int h = 0; h < 2; h++) {
            const int s = mi * 2 + h;
            float v[16], lm = -1e30f;
            #pragma unroll
            for (int ni = 0; ni < 8; ni++) {
                __half2 hv = *reinterpret_cast<__half2*>(&hacc[mi][ni][h]);
                float2 f = __half22float2(hv);
                v[ni * 2]     = f.x + bv[ni][0];
                v[ni * 2 + 1] = f.y + bv[ni][1];
                lm = fmaxf(lm, v[ni * 2]);
                lm = fmaxf(lm, v[ni * 2 + 1]);
            }
            float e = 0.f;
            #pragma unroll
            for (int j = 0; j < 16; j++) e += __expf(v[j] - lm);
            rm[s] = lm; rs[s] = e;
        }
    }

    // cross-thread reduction: quad shuffle, then across 4 N-warps via smem
    __syncthreads();
    float2* red = reinterpret_cast<float2*>(sptr);   // 128 rows x 4 warps
    #pragma unroll
    for (int s = 0; s < 8; s++) {
        float m = rm[s], sm = rs[s];
        #pragma unroll
        for (int d = 1; d <= 2; d <<= 1) {
            float om = __shfl_xor_sync(0xffffffffu, m, d);
            float os = __shfl_xor_sync(0xffffffffu, sm, d);
            float nm = fmaxf(m, om);
            sm = sm * __expf(m - nm) + os * __expf(om - nm);
            m = nm;
        }
        if (tg == 0) {
            const int mi = s >> 1, h = s & 1;
            const int row = warpM + mi * 16 + (lane >> 2) + h * 8;
            red[row * 4 + (wid & 3)] = make_float2(m, sm);
        }
    }
    __syncthreads();

    if (tid < BM) {
        float m = -1e30f, sm = 0.f;
        #pragma unroll
        for (int w = 0; w < 4; w++) {
            float2 p = red[tid * 4 + w];
            float nm = fmaxf(m, p.x);
            sm = sm * __expf(m - nm) + p.y * __expf(p.x - nm);
            m = nm;
        }
        g_part[(size_t)(m0 + tid) * 16 + ns] = make_float2(m, sm);
    }
}

// ---------------- combine partials + activations ----------------
__global__ void __launch_bounds__(256) combine_kernel(float* __restrict__ out) {
    const int i = blockIdx.x * 256 + threadIdx.x;
    if (i >= M_DIM) return;
    const float4* p4 = reinterpret_cast<const float4*>(g_part + (size_t)i * 16);
    float m = -1e30f, sm = 0.f;
    #pragma unroll
    for (int j = 0; j < 8; j++) {          // fixed order -> deterministic
        float4 q = p4[j];                  // (m0,s0,m1,s1)
        float nm = fmaxf(m, q.x);
        sm = sm * __expf(m - nm) + q.y * __expf(q.x - nm);
        m = nm;
        nm = fmaxf(m, q.z);
        sm = sm * __expf(m - nm) + q.w * __expf(q.z - nm);
        m = nm;
    }
    float v = m + logf(sm);
    v = v > 0.f ? v : 0.01f * v;           // LeakyReLU x2
    v = v > 0.f ? v : 0.01f * v;
    v = v * 0.5f * (1.0f + erff(v * 0.70710678118654752f));   // GELU x2
    v = v * 0.5f * (1.0f + erff(v * 0.70710678118654752f));
    out[i] = v;
}

extern "C" void kernel_launch(void* const* d_in, const int* in_sizes, int n_in,
                              void* d_out, int out_size) {
    const float* x = (const float*)d_in[0];
    const float* W = (const float*)d_in[1];
    const float* b = (const float*)d_in[2];
    float* out = (float*)d_out;

    cudaFuncSetAttribute(gemm_lse_part_kernel,
                         cudaFuncAttributeMaxDynamicSharedMemorySize, SMEM_BYTES);

    const int x8 = (M_DIM * K_DIM) / 8;
    const int w8 = (N_DIM * K_DIM) / 8;
    cvt_xw_kernel<<<(x8 + w8 + 255) / 256, 256>>>((const float4*)x, x8,
                                                  (const float4*)W, w8);
    gemm_lse_part_kernel<<<(M_DIM / BM) * NSLICE, 256, SMEM_BYTES>>>(b);
    combine_kernel<<<(M_DIM + 255) / 256, 256>>>(out);
}

// round 14
// speedup vs baseline: 1.0230x; 1.0230x over previous
#include <cuda_runtime.h>
#include <cuda_fp16.h>
#include <cstdint>
#include <math.h>

#define M_DIM 16384
#define K_DIM 4096
#define N_DIM 4096

// fp16 copies of inputs + lse partials (static device scratch)
static __device__ __half g_xh[(size_t)M_DIM * K_DIM];
static __device__ __half g_wh[(size_t)N_DIM * K_DIM];
static __device__ float2 g_part[(size_t)M_DIM * 16];  // [row][nslice] (max,sum)

// ---------------- tile / smem geometry ----------------
constexpr int BM = 128;            // M tile per CTA
constexpr int BN = 256;            // N cols per CTA (single chunk)
constexpr int NSLICE = 16;         // N split across CTAs
constexpr int BK = 64;             // K halves per stage (128 B/row, SW128)
constexpr int NSTAGE = 2;
constexpr int TOTSTG = K_DIM / BK;           // 64 stages per CTA

constexpr uint32_t A_STG = BM * 128;         // 16 KB
constexpr uint32_t B_STG = BN * 128;         // 32 KB
constexpr uint32_t STG   = A_STG + B_STG;    // 48 KB
constexpr uint32_t SMEM_BYTES = NSTAGE * STG + 1024;   // 99328 -> 2 CTAs/SM

__device__ __forceinline__ uint32_t smem_u32(const void* p) {
    uint32_t a;
    asm("{ .reg .u64 t; cvta.to.shared.u64 t, %1; cvt.u32.u64 %0, t; }"
        : "=r"(a) : "l"(p));
    return a;
}
__device__ __forceinline__ uint32_t swz(uint32_t off) {   // SW128, 16B granule
    return off ^ ((off >> 3) & 0x70);
}
__device__ __forceinline__ uint32_t h2_bits(__half2 h) {
    return *reinterpret_cast<uint32_t*>(&h);
}
__device__ __forceinline__ void cp_async16(uint32_t dst, const void* src) {
    asm volatile("cp.async.cg.shared.global [%0], [%1], 16;"
                 :: "r"(dst), "l"(__cvta_generic_to_global(src)) : "memory");
}
#define CP_COMMIT() asm volatile("cp.async.commit_group;" ::: "memory")
#define CP_WAIT(n)  asm volatile("cp.async.wait_group %0;" :: "n"(n) : "memory")

__device__ __forceinline__ void ldsm4(uint32_t* r, uint32_t addr) {
    asm volatile("ldmatrix.sync.aligned.m8n8.x4.shared.b16 {%0,%1,%2,%3}, [%4];"
                 : "=r"(r[0]), "=r"(r[1]), "=r"(r[2]), "=r"(r[3]) : "r"(addr));
}
// fp16-accumulate MMA: D/C are 2 b32 regs (4 halves)
__device__ __forceinline__ void mma16816_h(uint32_t* c, const uint32_t* a, const uint32_t* b) {
    asm volatile(
        "mma.sync.aligned.m16n8k16.row.col.f16.f16.f16.f16 "
        "{%0,%1}, {%2,%3,%4,%5}, {%6,%7}, {%0,%1};"
        : "+r"(c[0]), "+r"(c[1])
        : "r"(a[0]), "r"(a[1]), "r"(a[2]), "r"(a[3]), "r"(b[0]), "r"(b[1]));
}

// ---------------- fp32 -> fp16 conversion: x and W in ONE launch ----------------
__global__ void __launch_bounds__(256)
cvt_xw_kernel(const float4* __restrict__ xs, int nx8,
              const float4* __restrict__ ws, int nw8) {
    const int i = blockIdx.x * 256 + threadIdx.x;
    const float4* src;
    uint4* dst;
    int idx;
    if (i < nx8) {
        src = xs; dst = reinterpret_cast<uint4*>(g_xh); idx = i;
    } else {
        idx = i - nx8;
        if (idx >= nw8) return;
        src = ws; dst = reinterpret_cast<uint4*>(g_wh);
    }
    float4 a = src[2 * idx], b = src[2 * idx + 1];
    uint4 o;
    o.x = h2_bits(__floats2half2_rn(a.x, a.y));
    o.y = h2_bits(__floats2half2_rn(a.z, a.w));
    o.z = h2_bits(__floats2half2_rn(b.x, b.y));
    o.w = h2_bits(__floats2half2_rn(b.z, b.w));
    dst[idx] = o;
}

// ---------------- GEMM + partial logsumexp (per N-slice) ----------------
__global__ void __launch_bounds__(256, 2)
gemm_lse_part_kernel(const float* __restrict__ bias) {
    extern __shared__ char smem_raw[];
    const uint32_t sb0 = smem_u32(smem_raw);
    const uint32_t sb  = (sb0 + 1023u) & ~1023u;   // 1024-align
    char* sptr = smem_raw + (sb - sb0);

    const int tid  = threadIdx.x;
    const int wid  = tid >> 5;            // 0..7
    const int lane = tid & 31;
    const int mt   = blockIdx.x >> 4;     // m-tile (16 consecutive CTAs share A)
    const int ns   = blockIdx.x & 15;     // n-slice
    const int m0   = mt * BM;
    const int n0   = ns * BN;

    const int warpM = (wid >> 2) * 64;    // 0 or 64
    const int warpN = (wid & 3) * 64;     // 0,64,128,192 within BN

    // per-lane ldmatrix byte offsets (pre-swizzle)
    const int matid = lane >> 3, rin = lane & 7;
    int aRow[4], bRow[4];
    #pragma unroll
    for (int mi = 0; mi < 4; mi++)
        aRow[mi] = (warpM + mi * 16 + (matid & 1) * 8 + rin) * 128 + (matid >> 1) * 16;
    #pragma unroll
    for (int p = 0; p < 4; p++)
        bRow[p] = (warpN + p * 16 + (matid >> 1) * 8 + rin) * 128 + (matid & 1) * 16;

    // ---- producer addressing (uniform strides) ----
    const int prow  = tid >> 3;
    const int pc16  = tid & 7;
    const char* srcA = (const char*)(g_xh + ((size_t)(m0 + prow) * K_DIM + pc16 * 8));
    const char* srcB = (const char*)(g_wh + ((size_t)(n0 + prow) * K_DIM + pc16 * 8));
    const uint32_t dstOff = swz((uint32_t)(prow * 128 + pc16 * 16));  // +4096/j commutes

    auto issue_stage = [&](int gs) {
        if (gs < TOTSTG) {
            const uint32_t offK = (uint32_t)gs << 7;   // gs * 128 B into each row
            const uint32_t base = sb + (uint32_t)(gs & 1) * STG;
            #pragma unroll
            for (int j = 0; j < 4; j++)
                cp_async16(base + dstOff + j * 4096,
                           srcA + offK + (size_t)j * (32 * K_DIM * 2));
            #pragma unroll
            for (int j = 0; j < 8; j++)
                cp_async16(base + A_STG + dstOff + j * 4096,
                           srcB + offK + (size_t)j * (32 * K_DIM * 2));
        }
        CP_COMMIT();
    };

    // fp16 accumulators: 4 m-tiles x 8 n-tiles x 2 regs
    uint32_t hacc[4][8][2];
    #pragma unroll
    for (int mi = 0; mi < 4; mi++)
        #pragma unroll
        for (int ni = 0; ni < 8; ni++) { hacc[mi][ni][0] = 0u; hacc[mi][ni][1] = 0u; }

    issue_stage(0);

    #pragma unroll 1
    for (int gs = 0; gs < TOTSTG; ++gs) {
        CP_WAIT(0);                            // stage gs complete (per-warp)
        __syncthreads();                       // visibility + all warps past gs-1
        issue_stage(gs + 1);                   // overwrites slot of gs-1 (safe)

        const uint32_t aB = sb + (uint32_t)(gs & 1) * STG;
        const uint32_t bB = aB + A_STG;
        #pragma unroll
        for (int g = 0; g < 4; g++) {
            uint32_t af[4][4], bt[4][4];
            #pragma unroll
            for (int mi = 0; mi < 4; mi++)
                ldsm4(af[mi], aB + swz((uint32_t)(aRow[mi] + g * 32)));
            #pragma unroll
            for (int p = 0; p < 4; p++)
                ldsm4(bt[p], bB + swz((uint32_t)(bRow[p] + g * 32)));
            #pragma unroll
            for (int mi = 0; mi < 4; mi++)
                #pragma unroll
                for (int p = 0; p < 4; p++) {
                    mma16816_h(hacc[mi][2 * p],     af[mi], &bt[p][0]);
                    mma16816_h(hacc[mi][2 * p + 1], af[mi], &bt[p][2]);
                }
        }
    }

    // fold logits (fp16 acc, K complete) into (max, sum)
    const int tg = lane & 3;
    float rm[8], rs[8];
    float bv[8][2];
    #pragma unroll
    for (int ni = 0; ni < 8; ni++) {
        const int nc = n0 + warpN + ni * 8 + tg * 2;
        bv[ni][0] = bias[nc];
        bv[ni][1] = bias[nc + 1];
    }
    #pragma unroll
    for (int mi = 0; mi < 4; mi++) {
        #pragma unroll
        for (int h = 0; h < 2; h++) {
            const int s = mi * 2 + h;
            float v[16], lm = -1e30f;
            #pragma unroll
            for (int ni = 0; ni < 8; ni++) {
                __half2 hv = *reinterpret_cast<__half2*>(&hacc[mi][ni][h]);
                float2 f = __half22float2(hv);
                v[ni * 2]     = f.x + bv[ni][0];
                v[ni * 2 + 1] = f.y + bv[ni][1];
                lm = fmaxf(lm, v[ni * 2]);
                lm = fmaxf(lm, v[ni * 2 + 1]);
            }
            float e = 0.f;
            #pragma unroll
            for (int j = 0; j < 16; j++) e += __expf(v[j] - lm);
            rm[s] = lm; rs[s] = e;
        }
    }

    // cross-thread reduction: quad shuffle, then across 4 N-warps via smem
    __syncthreads();
    float2* red = reinterpret_cast<float2*>(sptr);   // 128 rows x 4 warps
    #pragma unroll
    for (int s = 0; s < 8; s++) {
        float m = rm[s], sm = rs[s];
        #pragma unroll
        for (int d = 1; d <= 2; d <<= 1) {
            float om = __shfl_xor_sync(0xffffffffu, m, d);
            float os = __shfl_xor_sync(0xffffffffu, sm, d);
            float nm = fmaxf(m, om);
            sm = sm * __expf(m - nm) + os * __expf(om - nm);
            m = nm;
        }
        if (tg == 0) {
            const int mi = s >> 1, h = s & 1;
            const int row = warpM + mi * 16 + (lane >> 2) + h * 8;
            red[row * 4 + (wid & 3)] = make_float2(m, sm);
        }
    }
    __syncthreads();

    if (tid < BM) {
        float m = -1e30f, sm = 0.f;
        #pragma unroll
        for (int w = 0; w < 4; w++) {
            float2 p = red[tid * 4 + w];
            float nm = fmaxf(m, p.x);
            sm = sm * __expf(m - nm) + p.y * __expf(p.x - nm);
            m = nm;
        }
        g_part[(size_t)(m0 + tid) * 16 + ns] = make_float2(m, sm);
    }
}

// ---------------- combine partials + activations ----------------
__global__ void __launch_bounds__(256) combine_kernel(float* __restrict__ out) {
    const int i = blockIdx.x * 256 + threadIdx.x;
    if (i >= M_DIM) return;
    const float4* p4 = reinterpret_cast<const float4*>(g_part + (size_t)i * 16);
    float m = -1e30f, sm = 0.f;
    #pragma unroll
    for (int j = 0; j < 8; j++) {          // fixed order -> deterministic
        float4 q = p4[j];                  // (m0,s0,m1,s1)
        float nm = fmaxf(m, q.x);
        sm = sm * __expf(m - nm) + q.y * __expf(q.x - nm);
        m = nm;
        nm = fmaxf(m, q.z);
        sm = sm * __expf(m - nm) + q.w * __expf(q.z - nm);
        m = nm;
    }
    float v = m + logf(sm);
    v = v > 0.f ? v : 0.01f * v;           // LeakyReLU x2
    v = v > 0.f ? v : 0.01f * v;
    v = v * 0.5f * (1.0f + erff(v * 0.70710678118654752f));   // GELU x2
    v = v * 0.5f * (1.0f + erff(v * 0.70710678118654752f));
    out[i] = v;
}

extern "C" void kernel_launch(void* const* d_in, const int* in_sizes, int n_in,
                              void* d_out, int out_size) {
    const float* x = (const float*)d_in[0];
    const float* W = (const float*)d_in[1];
    const float* b = (const float*)d_in[2];
    float* out = (float*)d_out;

    cudaFuncSetAttribute(gemm_lse_part_kernel,
                         cudaFuncAttributeMaxDynamicSharedMemorySize, SMEM_BYTES);

    const int x8 = (M_DIM * K_DIM) / 8;
    const int w8 = (N_DIM * K_DIM) / 8;
    cvt_xw_kernel<<<(x8 + w8 + 255) / 256, 256>>>((const float4*)x, x8,
                                                  (const float4*)W, w8);
    gemm_lse_part_kernel<<<(M_DIM / BM) * NSLICE, 256, SMEM_BYTES>>>(b);
    combine_kernel<<<(M_DIM + 255) / 256, 256>>>(out);
}